// round 1
// baseline (speedup 1.0000x reference)
#include <cuda_runtime.h>

// IntDVF: scaling-and-squaring integration of a displacement field.
// ddf0 = dvf / 2^7 ; repeat 7x: ddf = ddf + warp(ddf, ddf)
// warp = trilinear sample of ddf (as a 3-channel image) at grid + ddf,
// with floor/floor+1 indices clipped to [0, 127].

#define DGRID 128
#define NVOX (2 * DGRID * DGRID * DGRID)   // 4,194,304 voxels (batch=2)
#define NTHREADS 256

// 50.3 MB ping-pong scratch (allocation-free: __device__ global).
__device__ float g_scratch[(size_t)NVOX * 3];

__global__ __launch_bounds__(NTHREADS)
void intdvf_step(const float* __restrict__ src, float* __restrict__ dst,
                 float scale) {
    int idx = blockIdx.x * NTHREADS + threadIdx.x;   // voxel index, z innermost
    // idx layout: b(1) x(7) y(7) z(7)
    int z = idx & (DGRID - 1);
    int y = (idx >> 7) & (DGRID - 1);
    int x = (idx >> 14) & (DGRID - 1);
    int b = idx >> 21;

    const float* __restrict__ bsrc = src + (size_t)b * (DGRID * DGRID * DGRID) * 3;
    size_t off = (size_t)idx * 3;

    // Center displacement (raw); scaled copy used for the sample location.
    float rx = src[off + 0];
    float ry = src[off + 1];
    float rz = src[off + 2];

    float lx = (float)x + rx * scale;
    float ly = (float)y + ry * scale;
    float lz = (float)z + rz * scale;

    float fx = floorf(lx), fy = floorf(ly), fz = floorf(lz);
    float wx1 = lx - fx, wy1 = ly - fy, wz1 = lz - fz;
    float wx0 = 1.0f - wx1, wy0 = 1.0f - wy1, wz0 = 1.0f - wz1;

    int jx = (int)fx, jy = (int)fy, jz = (int)fz;
    int ix0 = min(max(jx,     0), DGRID - 1);
    int ix1 = min(max(jx + 1, 0), DGRID - 1);
    int iy0 = min(max(jy,     0), DGRID - 1);
    int iy1 = min(max(jy + 1, 0), DGRID - 1);
    int iz0 = min(max(jz,     0), DGRID - 1);
    int iz1 = min(max(jz + 1, 0), DGRID - 1);

    // Precompute row/plane offsets (in floats) for the 4 (x,y) corners.
    size_t px0 = (size_t)ix0 * (DGRID * DGRID) * 3;
    size_t px1 = (size_t)ix1 * (DGRID * DGRID) * 3;
    size_t ry0 = (size_t)iy0 * DGRID * 3;
    size_t ry1 = (size_t)iy1 * DGRID * 3;
    size_t cz0 = (size_t)iz0 * 3;
    size_t cz1 = (size_t)iz1 * 3;

    float w00 = wx0 * wy0, w01 = wx0 * wy1, w10 = wx1 * wy0, w11 = wx1 * wy1;

    float ax = 0.f, ay = 0.f, az = 0.f;

    // 8 taps, z-pair inner (adjacent in memory -> same/neighbor L1 lines).
    {
        const float* p = bsrc + px0 + ry0;
        float w = w00 * wz0;
        ax = fmaf(w, p[cz0 + 0], ax); ay = fmaf(w, p[cz0 + 1], ay); az = fmaf(w, p[cz0 + 2], az);
        w = w00 * wz1;
        ax = fmaf(w, p[cz1 + 0], ax); ay = fmaf(w, p[cz1 + 1], ay); az = fmaf(w, p[cz1 + 2], az);
    }
    {
        const float* p = bsrc + px0 + ry1;
        float w = w01 * wz0;
        ax = fmaf(w, p[cz0 + 0], ax); ay = fmaf(w, p[cz0 + 1], ay); az = fmaf(w, p[cz0 + 2], az);
        w = w01 * wz1;
        ax = fmaf(w, p[cz1 + 0], ax); ay = fmaf(w, p[cz1 + 1], ay); az = fmaf(w, p[cz1 + 2], az);
    }
    {
        const float* p = bsrc + px1 + ry0;
        float w = w10 * wz0;
        ax = fmaf(w, p[cz0 + 0], ax); ay = fmaf(w, p[cz0 + 1], ay); az = fmaf(w, p[cz0 + 2], az);
        w = w10 * wz1;
        ax = fmaf(w, p[cz1 + 0], ax); ay = fmaf(w, p[cz1 + 1], ay); az = fmaf(w, p[cz1 + 2], az);
    }
    {
        const float* p = bsrc + px1 + ry1;
        float w = w11 * wz0;
        ax = fmaf(w, p[cz0 + 0], ax); ay = fmaf(w, p[cz0 + 1], ay); az = fmaf(w, p[cz0 + 2], az);
        w = w11 * wz1;
        ax = fmaf(w, p[cz1 + 0], ax); ay = fmaf(w, p[cz1 + 1], ay); az = fmaf(w, p[cz1 + 2], az);
    }

    // out = scale*center + scale*interp(raw)  (scale folds the /2^7 init into step 1)
    dst[off + 0] = scale * (rx + ax);
    dst[off + 1] = scale * (ry + ay);
    dst[off + 2] = scale * (rz + az);
}

extern "C" void kernel_launch(void* const* d_in, const int* in_sizes, int n_in,
                              void* d_out, int out_size) {
    const float* dvf = (const float*)d_in[0];
    float* out = (float*)d_out;

    float* scratch = nullptr;
    cudaGetSymbolAddress((void**)&scratch, g_scratch);

    const int nblocks = NVOX / NTHREADS;
    const float s0 = 1.0f / 128.0f;   // 1 / 2^NUM_STEPS

    // 7 steps; odd steps write d_out so the final result lands in d_out.
    intdvf_step<<<nblocks, NTHREADS>>>(dvf,     out,     s0);   // step 1 (fused /128)
    intdvf_step<<<nblocks, NTHREADS>>>(out,     scratch, 1.0f); // step 2
    intdvf_step<<<nblocks, NTHREADS>>>(scratch, out,     1.0f); // step 3
    intdvf_step<<<nblocks, NTHREADS>>>(out,     scratch, 1.0f); // step 4
    intdvf_step<<<nblocks, NTHREADS>>>(scratch, out,     1.0f); // step 5
    intdvf_step<<<nblocks, NTHREADS>>>(out,     scratch, 1.0f); // step 6
    intdvf_step<<<nblocks, NTHREADS>>>(scratch, out,     1.0f); // step 7
}

// round 2
// speedup vs baseline: 1.2990x; 1.2990x over previous
#include <cuda_runtime.h>

// IntDVF scaling-and-squaring, SoA-layout version.
// ddf0 = dvf / 2^7 ; repeat 7x: ddf = ddf + warp(ddf, ddf)
//
// Intermediate fields are stored channel-planar (SoA): plane c at [c*NVOX, (c+1)*NVOX).
// Within a plane, voxel index = b*D^3 + x*D^2 + y*D + z (z innermost).
// A pre-pass transposes the AoS input; the last step writes AoS to d_out.

#define D     128
#define D2    (D * D)
#define D3    (D * D * D)
#define NVOX  (2 * D3)          // 4,194,304 voxels (batch=2)
#define NT    256

// Two 50.3 MB SoA ping-pong buffers (allocation-free: __device__ globals).
__device__ float g_a[(size_t)NVOX * 3];
__device__ float g_b[(size_t)NVOX * 3];

__global__ __launch_bounds__(NT)
void aos2soa(const float* __restrict__ in, float* __restrict__ out) {
    int i = blockIdx.x * NT + threadIdx.x;
    size_t o = (size_t)i * 3;
    float vx = in[o + 0], vy = in[o + 1], vz = in[o + 2];
    out[i]            = vx;
    out[i + NVOX]     = vy;
    out[i + 2 * NVOX] = vz;
}

template<bool OUT_AOS>
__global__ __launch_bounds__(NT)
void intdvf_step(const float* __restrict__ src, float* __restrict__ dst,
                 float scale) {
    int idx = blockIdx.x * NT + threadIdx.x;
    int z = idx & (D - 1);
    int y = (idx >> 7) & (D - 1);
    int x = (idx >> 14) & (D - 1);
    int b = idx >> 21;

    // Coalesced SoA center read.
    float rx = src[idx];
    float ry = src[idx + NVOX];
    float rz = src[idx + 2 * NVOX];

    float lx = (float)x + rx * scale;
    float ly = (float)y + ry * scale;
    float lz = (float)z + rz * scale;

    float fx = floorf(lx), fy = floorf(ly), fz = floorf(lz);
    float wx1 = lx - fx, wy1 = ly - fy, wz1 = lz - fz;
    float wx0 = 1.0f - wx1, wy0 = 1.0f - wy1, wz0 = 1.0f - wz1;

    int jx = (int)fx, jy = (int)fy, jz = (int)fz;
    int ix0 = min(max(jx,     0), D - 1);
    int ix1 = min(max(jx + 1, 0), D - 1);
    int iy0 = min(max(jy,     0), D - 1);
    int iy1 = min(max(jy + 1, 0), D - 1);
    int iz0 = min(max(jz,     0), D - 1);
    int iz1 = min(max(jz + 1, 0), D - 1);

    int bb  = b * D3;
    int pX0 = ix0 * D2, pX1 = ix1 * D2;
    int rY0 = iy0 * D,  rY1 = iy1 * D;

    // 8 corner linear indices within one channel plane.
    int i000 = bb + pX0 + rY0 + iz0;
    int i001 = bb + pX0 + rY0 + iz1;
    int i010 = bb + pX0 + rY1 + iz0;
    int i011 = bb + pX0 + rY1 + iz1;
    int i100 = bb + pX1 + rY0 + iz0;
    int i101 = bb + pX1 + rY0 + iz1;
    int i110 = bb + pX1 + rY1 + iz0;
    int i111 = bb + pX1 + rY1 + iz1;

    float w00 = wx0 * wy0, w01 = wx0 * wy1, w10 = wx1 * wy0, w11 = wx1 * wy1;
    float w000 = w00 * wz0, w001 = w00 * wz1;
    float w010 = w01 * wz0, w011 = w01 * wz1;
    float w100 = w10 * wz0, w101 = w10 * wz1;
    float w110 = w11 * wz0, w111 = w11 * wz1;

    float acc[3];
    const float ctr[3] = {rx, ry, rz};

    #pragma unroll
    for (int c = 0; c < 3; c++) {
        const float* __restrict__ p = src + (size_t)c * NVOX;
        float a;
        a = w000 * __ldg(p + i000);
        a = fmaf(w001, __ldg(p + i001), a);
        a = fmaf(w010, __ldg(p + i010), a);
        a = fmaf(w011, __ldg(p + i011), a);
        a = fmaf(w100, __ldg(p + i100), a);
        a = fmaf(w101, __ldg(p + i101), a);
        a = fmaf(w110, __ldg(p + i110), a);
        a = fmaf(w111, __ldg(p + i111), a);
        acc[c] = scale * (ctr[c] + a);   // scale folds the /2^7 init into step 1
    }

    if (OUT_AOS) {
        size_t o = (size_t)idx * 3;
        dst[o + 0] = acc[0];
        dst[o + 1] = acc[1];
        dst[o + 2] = acc[2];
    } else {
        dst[idx]            = acc[0];
        dst[idx + NVOX]     = acc[1];
        dst[idx + 2 * NVOX] = acc[2];
    }
}

extern "C" void kernel_launch(void* const* d_in, const int* in_sizes, int n_in,
                              void* d_out, int out_size) {
    const float* dvf = (const float*)d_in[0];
    float* out = (float*)d_out;

    float* A = nullptr;
    float* Bf = nullptr;
    cudaGetSymbolAddress((void**)&A,  g_a);
    cudaGetSymbolAddress((void**)&Bf, g_b);

    const int nblocks = NVOX / NT;
    const float s0 = 1.0f / 128.0f;   // 1 / 2^NUM_STEPS

    aos2soa<<<nblocks, NT>>>(dvf, A);

    intdvf_step<false><<<nblocks, NT>>>(A,  Bf, s0);    // step 1 (fused /128)
    intdvf_step<false><<<nblocks, NT>>>(Bf, A,  1.0f);  // step 2
    intdvf_step<false><<<nblocks, NT>>>(A,  Bf, 1.0f);  // step 3
    intdvf_step<false><<<nblocks, NT>>>(Bf, A,  1.0f);  // step 4
    intdvf_step<false><<<nblocks, NT>>>(A,  Bf, 1.0f);  // step 5
    intdvf_step<false><<<nblocks, NT>>>(Bf, A,  1.0f);  // step 6
    intdvf_step<true ><<<nblocks, NT>>>(A,  out, 1.0f); // step 7 -> AoS d_out
}